// round 1
// baseline (speedup 1.0000x reference)
#include <cuda_runtime.h>

typedef unsigned long long u64;

#define DINL __device__ __forceinline__

DINL u64 pack2(float lo, float hi) {
    u64 r;
    asm("mov.b64 %0, {%1, %2};" : "=l"(r) : "r"(__float_as_uint(lo)), "r"(__float_as_uint(hi)));
    return r;
}
DINL void unpack2(u64 v, float& lo, float& hi) {
    unsigned int a, b;
    asm("mov.b64 {%0, %1}, %2;" : "=r"(a), "=r"(b) : "l"(v));
    lo = __uint_as_float(a);
    hi = __uint_as_float(b);
}
DINL u64 fma2(u64 a, u64 b, u64 c) {
    u64 d;
    asm("fma.rn.f32x2 %0, %1, %2, %3;" : "=l"(d) : "l"(a), "l"(b), "l"(c));
    return d;
}
DINL u64 add2(u64 a, u64 b) {
    u64 d;
    asm("add.rn.f32x2 %0, %1, %2;" : "=l"(d) : "l"(a), "l"(b));
    return d;
}

// Shapes (fixed by the problem): B=2, N=256, N1=N2=128, C=Co=16.
// h[b,n,j,k,o] = relu(base[b,n,o] + U[b,j,o] + V[b,k,o])
//   base = x.(Wa - Wb - Wc) + b1 ;  U = x1.Wb ;  V = x2.Wc
// h2 = relu(h @ W2 + b2); out = concat(max_{j,k} h2[:, :8], mean_{j,k} h2[:, 8:])

__global__ void __launch_bounds__(256, 2)
ppr3_kernel(const float* __restrict__ x, const float* __restrict__ x1,
            const float* __restrict__ x2, const float* __restrict__ W1,
            const float* __restrict__ b1, const float* __restrict__ W2,
            const float* __restrict__ b2, float* __restrict__ out)
{
    __shared__ float sUb[128][16];   // base + U[j], per-j 16-vector
    __shared__ u64   sVp[16][64];    // V packed over k: entry [o][g*32+l] = {V[l+64g][o], V[l+64g+32][o]}
    __shared__ u64   sW2p[16][8];    // W2 row o packed over p pairs
    __shared__ u64   sB2p[8];        // b2 packed over p pairs
    __shared__ float sBase[16];
    __shared__ float sRed[8][16];

    const int bx  = blockIdx.x;          // bx = b*256 + n
    const int b   = bx >> 8;
    const int tid = threadIdx.x;
    const int lane = tid & 31;
    const int w    = tid >> 5;

    // ---------------- setup phase 1 ----------------
    if (tid < 128) {
        int o = tid >> 3, pp = tid & 7;
        sW2p[o][pp] = pack2(W2[o * 16 + 2 * pp], W2[o * 16 + 2 * pp + 1]);
    } else if (tid < 136) {
        int pp = tid - 128;
        sB2p[pp] = pack2(b2[2 * pp], b2[2 * pp + 1]);
    } else if (tid < 152) {
        int o = tid - 136;
        float s = b1[o];
        const float* xr = x + bx * 16;
        #pragma unroll
        for (int c = 0; c < 16; c++)
            s += xr[c] * (W1[c * 16 + o] - W1[(16 + c) * 16 + o] - W1[(32 + c) * 16 + o]);
        sBase[o] = s;
    }

    // U = x1 . Wb  (2048 entries)
    const float* x1b = x1 + b * 128 * 16;
    for (int idx = tid; idx < 2048; idx += 256) {
        int j = idx >> 4, o = idx & 15;
        const float* xr = x1b + j * 16;
        float s = 0.f;
        #pragma unroll
        for (int c = 0; c < 16; c++) s += xr[c] * W1[(16 + c) * 16 + o];
        sUb[j][o] = s;
    }
    // V = x2 . Wc, stored pre-packed as f32x2 over (k, k+32)
    const float* x2b = x2 + b * 128 * 16;
    for (int idx = tid; idx < 1024; idx += 256) {
        int o = idx >> 6, kk = idx & 63;
        int g = kk >> 5, l = kk & 31;
        int klo = l + 64 * g, khi = klo + 32;
        const float* rlo = x2b + klo * 16;
        const float* rhi = x2b + khi * 16;
        float slo = 0.f, shi = 0.f;
        #pragma unroll
        for (int c = 0; c < 16; c++) {
            float wv = W1[(32 + c) * 16 + o];
            slo += rlo[c] * wv;
            shi += rhi[c] * wv;
        }
        sVp[o][kk] = pack2(slo, shi);
    }
    __syncthreads();
    // fold base into Ub
    for (int idx = tid; idx < 2048; idx += 256) {
        int j = idx >> 4, o = idx & 15;
        sUb[j][o] += sBase[o];
    }
    __syncthreads();

    // ---------------- main loop ----------------
    u64 b2r[8];
    #pragma unroll
    for (int pp = 0; pp < 8; pp++) b2r[pp] = sB2p[pp];

    float mx[8];
    #pragma unroll
    for (int p = 0; p < 8; p++) mx[p] = 0.f;   // relu(max z) = max(0, z...) so 0-init is exact
    u64 sm[4];
    u64 zero2 = pack2(0.f, 0.f);
    #pragma unroll
    for (int i = 0; i < 4; i++) sm[i] = zero2;

    for (int jj = 0; jj < 16; jj++) {
        const int j = (w << 4) + jj;
        float wv[16];
        #pragma unroll
        for (int o = 0; o < 16; o++) wv[o] = sUb[j][o];

        #pragma unroll
        for (int g = 0; g < 2; g++) {
            u64 z0[8], z1[8];
            #pragma unroll
            for (int pp = 0; pp < 8; pp++) { z0[pp] = b2r[pp]; z1[pp] = b2r[pp]; }

            #pragma unroll
            for (int o = 0; o < 16; o++) {
                u64 vp = sVp[o][(g << 5) + lane];
                float v0, v1;
                unpack2(vp, v0, v1);
                float t0 = fmaxf(wv[o] + v0, 0.f);   // relu(base + U[j] + V[k])
                float t1 = fmaxf(wv[o] + v1, 0.f);
                u64 tp0 = pack2(t0, t0);
                u64 tp1 = pack2(t1, t1);
                #pragma unroll
                for (int pp = 0; pp < 8; pp++) {
                    u64 w2 = sW2p[o][pp];
                    z0[pp] = fma2(tp0, w2, z0[pp]);
                    z1[pp] = fma2(tp1, w2, z1[pp]);
                }
            }
            // epilogue: p<8 -> running max (relu folded into 0-init),
            //           p>=8 -> running sum of relu(z)
            #pragma unroll
            for (int pp = 0; pp < 4; pp++) {
                float a0, a1, c0, c1;
                unpack2(z0[pp], a0, a1);
                unpack2(z1[pp], c0, c1);
                mx[2 * pp]     = fmaxf(mx[2 * pp],     fmaxf(a0, c0));
                mx[2 * pp + 1] = fmaxf(mx[2 * pp + 1], fmaxf(a1, c1));
            }
            #pragma unroll
            for (int pp = 4; pp < 8; pp++) {
                float a0, a1, c0, c1;
                unpack2(z0[pp], a0, a1);
                unpack2(z1[pp], c0, c1);
                u64 r0 = pack2(fmaxf(a0, 0.f), fmaxf(a1, 0.f));
                u64 r1 = pack2(fmaxf(c0, 0.f), fmaxf(c1, 0.f));
                sm[pp - 4] = add2(sm[pp - 4], add2(r0, r1));
            }
        }
    }

    // ---------------- reductions ----------------
    float sv[8];
    #pragma unroll
    for (int i = 0; i < 4; i++) unpack2(sm[i], sv[2 * i], sv[2 * i + 1]);

    #pragma unroll
    for (int off = 16; off; off >>= 1) {
        #pragma unroll
        for (int p = 0; p < 8; p++) {
            mx[p] = fmaxf(mx[p], __shfl_xor_sync(0xffffffffu, mx[p], off));
            sv[p] += __shfl_xor_sync(0xffffffffu, sv[p], off);
        }
    }
    if (lane == 0) {
        #pragma unroll
        for (int p = 0; p < 8; p++) {
            sRed[w][p]     = mx[p];
            sRed[w][8 + p] = sv[p];
        }
    }
    __syncthreads();
    if (tid < 16) {
        float r;
        if (tid < 8) {
            r = sRed[0][tid];
            #pragma unroll
            for (int ww = 1; ww < 8; ww++) r = fmaxf(r, sRed[ww][tid]);
        } else {
            r = 0.f;
            #pragma unroll
            for (int ww = 0; ww < 8; ww++) r += sRed[ww][tid];
            r *= (1.0f / 16384.0f);
        }
        out[bx * 16 + tid] = r;
    }
}

extern "C" void kernel_launch(void* const* d_in, const int* in_sizes, int n_in,
                              void* d_out, int out_size)
{
    const float* x  = (const float*)d_in[0];
    const float* x1 = (const float*)d_in[1];
    const float* x2 = (const float*)d_in[2];
    const float* W1 = (const float*)d_in[3];
    const float* b1 = (const float*)d_in[4];
    const float* W2 = (const float*)d_in[5];
    const float* b2 = (const float*)d_in[6];

    const int grid = in_sizes[0] / 16;   // B*N = 512
    ppr3_kernel<<<grid, 256>>>(x, x1, x2, W1, b1, W2, b2, (float*)d_out);
}